// round 9
// baseline (speedup 1.0000x reference)
#include <cuda_runtime.h>
#include <math.h>
#include <stdint.h>

#define SEQ   512
#define BATCH 128
#define INPD  256
#define HID   1024
#define G4    4096
#define TB    (SEQ*BATCH)   // 65536 rows

// ---- scratch (allocation-free: device globals) ----
__device__ float g_xproj[(size_t)TB * G4];   // 1 GiB: [T*B, 4H]
__device__ float g_hs[(size_t)TB * HID];     // 256 MiB: h per timestep (fp32)
__device__ float g_c[2][BATCH * HID];        // ping-pong cell state

__device__ __forceinline__ float sigmoidf_(float x) { return 1.0f / (1.0f + expf(-x)); }

// ============================================================================
// tf32 mma helpers (m16n8k8, 3xTF32 fp32-emulation)
// ============================================================================
__device__ __forceinline__ unsigned cvt_tf32(float x) {
    unsigned r;
    asm("cvt.rna.tf32.f32 %0, %1;" : "=r"(r) : "f"(x));
    return r;
}
__device__ __forceinline__ void split_tf32(float x, unsigned& hi, unsigned& lo) {
    hi = cvt_tf32(x);
    lo = cvt_tf32(x - __uint_as_float(hi));
}
__device__ __forceinline__ void mma_tf32(float* c, const unsigned* a, const unsigned* b) {
    asm volatile("mma.sync.aligned.m16n8k8.row.col.f32.tf32.tf32.f32 "
        "{%0,%1,%2,%3},{%4,%5,%6,%7},{%8,%9},{%0,%1,%2,%3};"
        : "+f"(c[0]), "+f"(c[1]), "+f"(c[2]), "+f"(c[3])
        : "r"(a[0]), "r"(a[1]), "r"(a[2]), "r"(a[3]), "r"(b[0]), "r"(b[1]));
}

extern __shared__ __align__(16) float smemf[];

// ============================================================================
// Generic 3xTF32 GEMM: C[M,N] = A[M,K] * B[N,K]^T + bias[N]
// (used for x_proj and out-proj; unchanged from R8 — proven)
// ============================================================================
#define GPITF 68
#define GEMM_SMEM ((128 + 64) * GPITF * 4)   // 52224 bytes

__launch_bounds__(256)
__global__ void gemm_tf32(const float* __restrict__ A,
                          const float* __restrict__ Bm,
                          const float* __restrict__ bias,
                          float* __restrict__ C,
                          int M, int N, int K) {
    float* As = smemf;                 // [128][GPITF]
    float* Bs = smemf + 128 * GPITF;   // [64][GPITF]

    const int tid    = threadIdx.x;
    const int lane   = tid & 31;
    const int wid    = tid >> 5;
    const int warp_m = wid >> 1;
    const int warp_n = wid & 1;
    const int row0   = blockIdx.y * 128;
    const int col0   = blockIdx.x * 64;

    float acc[2][4][4];
#pragma unroll
    for (int i = 0; i < 2; i++)
#pragma unroll
        for (int j = 0; j < 4; j++)
#pragma unroll
            for (int k = 0; k < 4; k++) acc[i][j][k] = 0.0f;

    for (int k0 = 0; k0 < K; k0 += 64) {
#pragma unroll
        for (int i = 0; i < 8; i++) {
            int idx = tid + i * 256;
            int r = idx >> 4, q = idx & 15;
            *(float4*)&As[r * GPITF + q * 4] =
                *(const float4*)(A + (size_t)(row0 + r) * K + k0 + q * 4);
        }
#pragma unroll
        for (int i = 0; i < 4; i++) {
            int idx = tid + i * 256;
            int r = idx >> 4, q = idx & 15;
            *(float4*)&Bs[r * GPITF + q * 4] =
                *(const float4*)(Bm + (size_t)(col0 + r) * K + k0 + q * 4);
        }
        __syncthreads();

#pragma unroll
        for (int kk = 0; kk < 64; kk += 8) {
            unsigned ahi[2][4], alo[2][4];
#pragma unroll
            for (int mt = 0; mt < 2; mt++) {
                int row = warp_m * 32 + mt * 16 + (lane >> 2);
                int c0  = kk + (lane & 3);
                split_tf32(As[row * GPITF + c0],           ahi[mt][0], alo[mt][0]);
                split_tf32(As[(row + 8) * GPITF + c0],     ahi[mt][1], alo[mt][1]);
                split_tf32(As[row * GPITF + c0 + 4],       ahi[mt][2], alo[mt][2]);
                split_tf32(As[(row + 8) * GPITF + c0 + 4], ahi[mt][3], alo[mt][3]);
            }
            unsigned bhi[4][2], blo[4][2];
#pragma unroll
            for (int nt = 0; nt < 4; nt++) {
                int brow = warp_n * 32 + nt * 8 + (lane >> 2);
                int bc   = kk + (lane & 3);
                split_tf32(Bs[brow * GPITF + bc],     bhi[nt][0], blo[nt][0]);
                split_tf32(Bs[brow * GPITF + bc + 4], bhi[nt][1], blo[nt][1]);
            }
#pragma unroll
            for (int mt = 0; mt < 2; mt++)
#pragma unroll
                for (int nt = 0; nt < 4; nt++) {
                    mma_tf32(acc[mt][nt], ahi[mt], bhi[nt]);
                    mma_tf32(acc[mt][nt], ahi[mt], blo[nt]);
                    mma_tf32(acc[mt][nt], alo[mt], bhi[nt]);
                }
        }
        __syncthreads();
    }

#pragma unroll
    for (int mt = 0; mt < 2; mt++)
#pragma unroll
        for (int nt = 0; nt < 4; nt++) {
            int row = row0 + warp_m * 32 + mt * 16 + (lane >> 2);
            int col = col0 + warp_n * 32 + nt * 8 + (lane & 3) * 2;
            float b0 = bias[col], b1 = bias[col + 1];
            *(float2*)(C + (size_t)row * N + col) =
                make_float2(acc[mt][nt][0] + b0, acc[mt][nt][1] + b1);
            *(float2*)(C + (size_t)(row + 8) * N + col) =
                make_float2(acc[mt][nt][2] + b0, acc[mt][nt][3] + b1);
        }
}

// ============================================================================
// LSTM step via 3xTF32. Pre-split hi/lo planes in smem (mainloop has ZERO
// cvt/fsub — fragments are raw-bit LDS). Register-prefetch pipeline over
// KC=64 chunks. 512 threads (16 warps: 4 warp_m x 4 warp_n), warp tile
// 32m x 8n. Grid: 128 CTAs; CTA = 128 batch rows x 32 packed gate-cols.
// Packed col l (0..31): j = bx*8 + l/4, gate g = l%4 (R7-validated mapping).
// ============================================================================
#define KCS   64
#define PITF  68                      // plane pitch (floats), conflict-free
#define A_PL  (128 * PITF)            // one A plane: 8704 floats
#define B_PL  (32 * PITF)             // one B plane: 2176 floats
#define STEP_SMEM ((2 * A_PL + 2 * B_PL) * 4)   // 87040 bytes

__launch_bounds__(512)
__global__ void lstm_step_tf32(int t,
                               const float* __restrict__ Whh,
                               const float* __restrict__ bhh) {
    const int tid    = threadIdx.x;
    const int lane   = tid & 31;
    const int wid    = tid >> 5;
    const int warp_m = wid >> 2;      // 0..3: m base warp_m*32
    const int warp_n = wid & 3;       // 0..3: n base warp_n*8
    const int bx     = blockIdx.x;

    float* Ahi = smemf;
    float* Alo = Ahi + A_PL;
    float* Bhi = Alo + A_PL;
    float* Blo = Bhi + B_PL;
    float* gsm = smemf;               // [128][34] staging, reuses planes after

    float acc[2][4];                  // [mt][4]
#pragma unroll
    for (int i = 0; i < 2; i++)
#pragma unroll
        for (int k = 0; k < 4; k++) acc[i][k] = 0.0f;

    if (t > 0) {
        const float* hprev = g_hs + (size_t)(t - 1) * BATCH * HID;

        // per-thread prefetch registers (chunk granularity)
        float4 rA[4];   // A: 2048 float4 / 512 thr = 4 each
        float4 rB;      // B: 512 float4 / 512 thr = 1 each
        const int arr[4] = { tid >> 4, (tid + 512) >> 4, (tid + 1024) >> 4, (tid + 1536) >> 4 };
        const int aq     = tid & 15;
        const int br     = tid >> 4;           // packed l 0..31
        const int bq     = tid & 15;
        const int b_nglob = (br & 3) * HID + bx * 8 + (br >> 2);

        // prologue: LDG chunk 0
#pragma unroll
        for (int i = 0; i < 4; i++)
            rA[i] = *(const float4*)(hprev + (size_t)arr[i] * HID + aq * 4);
        rB = *(const float4*)(Whh + (size_t)b_nglob * HID + bq * 4);

        for (int c = 0; c < HID / KCS; c++) {
            // ---- store current chunk regs into hi/lo planes (split here) ----
#pragma unroll
            for (int i = 0; i < 4; i++) {
                const float v[4] = { rA[i].x, rA[i].y, rA[i].z, rA[i].w };
                unsigned h4[4], l4[4];
#pragma unroll
                for (int e = 0; e < 4; e++) split_tf32(v[e], h4[e], l4[e]);
                *(uint4*)&Ahi[arr[i] * PITF + aq * 4] = make_uint4(h4[0], h4[1], h4[2], h4[3]);
                *(uint4*)&Alo[arr[i] * PITF + aq * 4] = make_uint4(l4[0], l4[1], l4[2], l4[3]);
            }
            {
                const float v[4] = { rB.x, rB.y, rB.z, rB.w };
                unsigned h4[4], l4[4];
#pragma unroll
                for (int e = 0; e < 4; e++) split_tf32(v[e], h4[e], l4[e]);
                *(uint4*)&Bhi[br * PITF + bq * 4] = make_uint4(h4[0], h4[1], h4[2], h4[3]);
                *(uint4*)&Blo[br * PITF + bq * 4] = make_uint4(l4[0], l4[1], l4[2], l4[3]);
            }
            __syncthreads();

            // ---- issue LDG for next chunk (latency hidden by compute) ----
            if (c + 1 < HID / KCS) {
                const int kc = (c + 1) * KCS;
#pragma unroll
                for (int i = 0; i < 4; i++)
                    rA[i] = *(const float4*)(hprev + (size_t)arr[i] * HID + kc + aq * 4);
                rB = *(const float4*)(Whh + (size_t)b_nglob * HID + kc + bq * 4);
            }

            // ---- mainloop: pure LDS + MMA ----
#pragma unroll
            for (int kk = 0; kk < KCS; kk += 8) {
                unsigned ahi[2][4], alo[2][4], bhi[2], blo[2];
#pragma unroll
                for (int mt = 0; mt < 2; mt++) {
                    int row = warp_m * 32 + mt * 16 + (lane >> 2);
                    int c0  = kk + (lane & 3);
                    ahi[mt][0] = *(unsigned*)&Ahi[row * PITF + c0];
                    ahi[mt][1] = *(unsigned*)&Ahi[(row + 8) * PITF + c0];
                    ahi[mt][2] = *(unsigned*)&Ahi[row * PITF + c0 + 4];
                    ahi[mt][3] = *(unsigned*)&Ahi[(row + 8) * PITF + c0 + 4];
                    alo[mt][0] = *(unsigned*)&Alo[row * PITF + c0];
                    alo[mt][1] = *(unsigned*)&Alo[(row + 8) * PITF + c0];
                    alo[mt][2] = *(unsigned*)&Alo[row * PITF + c0 + 4];
                    alo[mt][3] = *(unsigned*)&Alo[(row + 8) * PITF + c0 + 4];
                }
                {
                    int brow = warp_n * 8 + (lane >> 2);
                    int bc   = kk + (lane & 3);
                    bhi[0] = *(unsigned*)&Bhi[brow * PITF + bc];
                    bhi[1] = *(unsigned*)&Bhi[brow * PITF + bc + 4];
                    blo[0] = *(unsigned*)&Blo[brow * PITF + bc];
                    blo[1] = *(unsigned*)&Blo[brow * PITF + bc + 4];
                }
#pragma unroll
                for (int mt = 0; mt < 2; mt++) {
                    mma_tf32(acc[mt], ahi[mt], bhi);
                    mma_tf32(acc[mt], ahi[mt], blo);
                    mma_tf32(acc[mt], alo[mt], bhi);
                }
            }
            __syncthreads();
        }
    } else {
        __syncthreads();
    }

    // stage gate pre-activations: gsm[b][l], pitch 34
#pragma unroll
    for (int mt = 0; mt < 2; mt++) {
        int row = warp_m * 32 + mt * 16 + (lane >> 2);
        int col = warp_n * 8 + (lane & 3) * 2;
        *(float2*)(gsm + row * 34 + col) = make_float2(acc[mt][0], acc[mt][1]);
        *(float2*)(gsm + (row + 8) * 34 + col) = make_float2(acc[mt][2], acc[mt][3]);
    }
    __syncthreads();

    // fused activation epilogue: 1024 (b, jj) items / 512 threads
    const float* xp   = g_xproj + (size_t)t * BATCH * G4;
    const float* cin  = g_c[t & 1];
    float*       cout = g_c[(t + 1) & 1];
    float*       hout = g_hs + (size_t)t * BATCH * HID;

#pragma unroll
    for (int it = 0; it < 2; it++) {
        int item = tid + it * 512;
        int b    = item & 127;
        int jj   = item >> 7;           // 0..7
        int j    = bx * 8 + jj;
        size_t xb = (size_t)b * G4 + j;
        float gi = gsm[b * 34 + jj * 4 + 0] + xp[xb]           + bhh[j];
        float gf = gsm[b * 34 + jj * 4 + 1] + xp[xb + HID]     + bhh[HID + j];
        float gg = gsm[b * 34 + jj * 4 + 2] + xp[xb + 2 * HID] + bhh[2 * HID + j];
        float go = gsm[b * 34 + jj * 4 + 3] + xp[xb + 3 * HID] + bhh[3 * HID + j];
        float cold = (t > 0) ? cin[b * HID + j] : 0.0f;
        float cn = sigmoidf_(gf) * cold + sigmoidf_(gi) * tanhf(gg);
        float hn = sigmoidf_(go) * tanhf(cn);
        cout[b * HID + j] = cn;
        hout[(size_t)b * HID + j] = hn;
    }
}

// ============================================================================
// In-place row-wise log_softmax over 256 columns. One block per row.
// ============================================================================
__launch_bounds__(256)
__global__ void logsoftmax_kernel(float* __restrict__ out) {
    __shared__ float red[256];
    const size_t r = blockIdx.x;
    const int tid  = threadIdx.x;
    float v = out[r * 256 + tid];

    red[tid] = v;
    __syncthreads();
#pragma unroll
    for (int s = 128; s > 0; s >>= 1) {
        if (tid < s) red[tid] = fmaxf(red[tid], red[tid + s]);
        __syncthreads();
    }
    float m = red[0];
    __syncthreads();

    float e = expf(v - m);
    red[tid] = e;
    __syncthreads();
#pragma unroll
    for (int s = 128; s > 0; s >>= 1) {
        if (tid < s) red[tid] += red[tid + s];
        __syncthreads();
    }
    float lse = logf(red[0]) + m;
    out[r * 256 + tid] = v - lse;
}

// ============================================================================
extern "C" void kernel_launch(void* const* d_in, const int* in_sizes, int n_in,
                              void* d_out, int out_size) {
    const float* inp  = (const float*)d_in[0];  // [512,128,256]
    const float* Wxh  = (const float*)d_in[1];  // [4096,256]
    const float* bxh  = (const float*)d_in[2];  // [4096]
    const float* Whh  = (const float*)d_in[3];  // [4096,1024]
    const float* bhh  = (const float*)d_in[4];  // [4096]
    const float* Wout = (const float*)d_in[5];  // [256,1024]
    const float* bout = (const float*)d_in[6];  // [256]
    float* out = (float*)d_out;                 // [512,128,256] fp32

    float* xproj; cudaGetSymbolAddress((void**)&xproj, g_xproj);
    float* hs;    cudaGetSymbolAddress((void**)&hs, g_hs);

    cudaFuncSetAttribute(lstm_step_tf32,
                         cudaFuncAttributeMaxDynamicSharedMemorySize, STEP_SMEM);
    cudaFuncSetAttribute(gemm_tf32,
                         cudaFuncAttributeMaxDynamicSharedMemorySize, GEMM_SMEM);

    // 1) x_proj[T*B, 4H] = inp @ Wxh^T + bxh  (3xTF32)
    gemm_tf32<<<dim3(G4 / 64, TB / 128), 256, GEMM_SMEM>>>(
        inp, Wxh, bxh, xproj, TB, G4, INPD);

    // 2) recurrence (3xTF32, pre-split smem planes, reg-prefetch pipeline)
    for (int t = 0; t < SEQ; t++)
        lstm_step_tf32<<<128, 512, STEP_SMEM>>>(t, Whh, bhh);

    // 3) out[T*B, 256] = hs @ Wout^T + bout  (3xTF32)
    gemm_tf32<<<dim3(INPD / 64, TB / 128), 256, GEMM_SMEM>>>(
        hs, Wout, bout, out, TB, INPD, HID);

    // 4) log_softmax rows
    logsoftmax_kernel<<<TB, 256>>>(out);
}

// round 10
// speedup vs baseline: 1.1760x; 1.1760x over previous
#include <cuda_runtime.h>
#include <math.h>
#include <stdint.h>

#define SEQ   512
#define BATCH 128
#define INPD  256
#define HID   1024
#define G4    4096
#define TB    (SEQ*BATCH)   // 65536 rows

// ---- scratch (allocation-free: device globals) ----
__device__ float g_xproj[(size_t)TB * G4];   // 1 GiB: [T*B, 4H]
__device__ float g_hs[(size_t)TB * HID];     // 256 MiB: h per timestep (fp32)
__device__ float g_c[2][BATCH * HID];        // ping-pong cell state

__device__ __forceinline__ float sigmoidf_(float x) { return 1.0f / (1.0f + expf(-x)); }

// ============================================================================
// tf32 mma helpers (m16n8k8, 3xTF32 fp32-emulation)
// ============================================================================
__device__ __forceinline__ unsigned cvt_tf32(float x) {
    unsigned r;
    asm("cvt.rna.tf32.f32 %0, %1;" : "=r"(r) : "f"(x));
    return r;
}
__device__ __forceinline__ void split_tf32(float x, unsigned& hi, unsigned& lo) {
    hi = cvt_tf32(x);
    lo = cvt_tf32(x - __uint_as_float(hi));
}
__device__ __forceinline__ void mma_tf32(float* c, const unsigned* a, const unsigned* b) {
    asm volatile("mma.sync.aligned.m16n8k8.row.col.f32.tf32.tf32.f32 "
        "{%0,%1,%2,%3},{%4,%5,%6,%7},{%8,%9},{%0,%1,%2,%3};"
        : "+f"(c[0]), "+f"(c[1]), "+f"(c[2]), "+f"(c[3])
        : "r"(a[0]), "r"(a[1]), "r"(a[2]), "r"(a[3]), "r"(b[0]), "r"(b[1]));
}

extern __shared__ __align__(16) float smemf[];

// ============================================================================
// Generic 3xTF32 GEMM: C[M,N] = A[M,K] * B[N,K]^T + bias[N]
// (x_proj and out-proj; unchanged — proven)
// ============================================================================
#define GPITF 68
#define GEMM_SMEM ((128 + 64) * GPITF * 4)   // 52224 bytes

__launch_bounds__(256)
__global__ void gemm_tf32(const float* __restrict__ A,
                          const float* __restrict__ Bm,
                          const float* __restrict__ bias,
                          float* __restrict__ C,
                          int M, int N, int K) {
    float* As = smemf;                 // [128][GPITF]
    float* Bs = smemf + 128 * GPITF;   // [64][GPITF]

    const int tid    = threadIdx.x;
    const int lane   = tid & 31;
    const int wid    = tid >> 5;
    const int warp_m = wid >> 1;
    const int warp_n = wid & 1;
    const int row0   = blockIdx.y * 128;
    const int col0   = blockIdx.x * 64;

    float acc[2][4][4];
#pragma unroll
    for (int i = 0; i < 2; i++)
#pragma unroll
        for (int j = 0; j < 4; j++)
#pragma unroll
            for (int k = 0; k < 4; k++) acc[i][j][k] = 0.0f;

    for (int k0 = 0; k0 < K; k0 += 64) {
#pragma unroll
        for (int i = 0; i < 8; i++) {
            int idx = tid + i * 256;
            int r = idx >> 4, q = idx & 15;
            *(float4*)&As[r * GPITF + q * 4] =
                *(const float4*)(A + (size_t)(row0 + r) * K + k0 + q * 4);
        }
#pragma unroll
        for (int i = 0; i < 4; i++) {
            int idx = tid + i * 256;
            int r = idx >> 4, q = idx & 15;
            *(float4*)&Bs[r * GPITF + q * 4] =
                *(const float4*)(Bm + (size_t)(col0 + r) * K + k0 + q * 4);
        }
        __syncthreads();

#pragma unroll
        for (int kk = 0; kk < 64; kk += 8) {
            unsigned ahi[2][4], alo[2][4];
#pragma unroll
            for (int mt = 0; mt < 2; mt++) {
                int row = warp_m * 32 + mt * 16 + (lane >> 2);
                int c0  = kk + (lane & 3);
                split_tf32(As[row * GPITF + c0],           ahi[mt][0], alo[mt][0]);
                split_tf32(As[(row + 8) * GPITF + c0],     ahi[mt][1], alo[mt][1]);
                split_tf32(As[row * GPITF + c0 + 4],       ahi[mt][2], alo[mt][2]);
                split_tf32(As[(row + 8) * GPITF + c0 + 4], ahi[mt][3], alo[mt][3]);
            }
            unsigned bhi[4][2], blo[4][2];
#pragma unroll
            for (int nt = 0; nt < 4; nt++) {
                int brow = warp_n * 32 + nt * 8 + (lane >> 2);
                int bc   = kk + (lane & 3);
                split_tf32(Bs[brow * GPITF + bc],     bhi[nt][0], blo[nt][0]);
                split_tf32(Bs[brow * GPITF + bc + 4], bhi[nt][1], blo[nt][1]);
            }
#pragma unroll
            for (int mt = 0; mt < 2; mt++)
#pragma unroll
                for (int nt = 0; nt < 4; nt++) {
                    mma_tf32(acc[mt][nt], ahi[mt], bhi[nt]);
                    mma_tf32(acc[mt][nt], ahi[mt], blo[nt]);
                    mma_tf32(acc[mt][nt], alo[mt], bhi[nt]);
                }
        }
        __syncthreads();
    }

#pragma unroll
    for (int mt = 0; mt < 2; mt++)
#pragma unroll
        for (int nt = 0; nt < 4; nt++) {
            int row = row0 + warp_m * 32 + mt * 16 + (lane >> 2);
            int col = col0 + warp_n * 32 + nt * 8 + (lane & 3) * 2;
            float b0 = bias[col], b1 = bias[col + 1];
            *(float2*)(C + (size_t)row * N + col) =
                make_float2(acc[mt][nt][0] + b0, acc[mt][nt][1] + b1);
            *(float2*)(C + (size_t)(row + 8) * N + col) =
                make_float2(acc[mt][nt][2] + b0, acc[mt][nt][3] + b1);
        }
}

// ============================================================================
// LSTM step via 3xTF32. Pre-split hi/lo planes in smem; register-prefetch
// pipeline over KC=64 chunks. 512 threads = 16 warps: 4 warp_m x 4-way
// K-split (ks). Warp tile 32m x 32n (mt=2, nt=4) -> 171 B smem per MMA
// (2.5x less than R9). 4 K-partials combined in smem staging.
// Grid: 128 CTAs; CTA = 128 batch rows x 32 packed gate-cols.
// Packed col l (0..31): j = bx*8 + l/4, gate g = l%4 (R7-validated mapping).
// ============================================================================
#define KCS   64
#define PITF  68                      // plane pitch (floats), conflict-free
#define A_PL  (128 * PITF)            // one A plane: 8704 floats
#define B_PL  (32 * PITF)             // one B plane: 2176 floats
#define STEP_SMEM ((2 * A_PL + 2 * B_PL) * 4)   // 87040 bytes
#define GSM_P (128 * 34)              // one staging partial: 4352 floats

__launch_bounds__(512)
__global__ void lstm_step_tf32(int t,
                               const float* __restrict__ Whh,
                               const float* __restrict__ bhh) {
    const int tid    = threadIdx.x;
    const int lane   = tid & 31;
    const int wid    = tid >> 5;
    const int warp_m = wid >> 2;      // 0..3: m base warp_m*32
    const int ks     = wid & 3;       // 0..3: K-split slice
    const int bx     = blockIdx.x;

    float* Ahi = smemf;
    float* Alo = Ahi + A_PL;
    float* Bhi = Alo + A_PL;
    float* Blo = Bhi + B_PL;
    float* gsm = smemf;               // [4][128][34] partials, reuses planes

    float acc[2][4][4];               // [mt][nt][4]
#pragma unroll
    for (int i = 0; i < 2; i++)
#pragma unroll
        for (int j = 0; j < 4; j++)
#pragma unroll
            for (int k = 0; k < 4; k++) acc[i][j][k] = 0.0f;

    if (t > 0) {
        const float* hprev = g_hs + (size_t)(t - 1) * BATCH * HID;

        // per-thread prefetch registers (chunk granularity)
        float4 rA[4];   // A: 2048 float4 / 512 thr = 4 each
        float4 rB;      // B: 512 float4 / 512 thr = 1 each
        const int arr[4] = { tid >> 4, (tid + 512) >> 4,
                             (tid + 1024) >> 4, (tid + 1536) >> 4 };
        const int aq = tid & 15;
        const int br = tid >> 4;            // packed l 0..31
        const int bq = tid & 15;
        const int b_nglob = (br & 3) * HID + bx * 8 + (br >> 2);

        // prologue: LDG chunk 0
#pragma unroll
        for (int i = 0; i < 4; i++)
            rA[i] = *(const float4*)(hprev + (size_t)arr[i] * HID + aq * 4);
        rB = *(const float4*)(Whh + (size_t)b_nglob * HID + bq * 4);

        for (int c = 0; c < HID / KCS; c++) {
            // ---- split current chunk regs into hi/lo planes ----
#pragma unroll
            for (int i = 0; i < 4; i++) {
                const float v[4] = { rA[i].x, rA[i].y, rA[i].z, rA[i].w };
                unsigned h4[4], l4[4];
#pragma unroll
                for (int e = 0; e < 4; e++) split_tf32(v[e], h4[e], l4[e]);
                *(uint4*)&Ahi[arr[i] * PITF + aq * 4] = make_uint4(h4[0], h4[1], h4[2], h4[3]);
                *(uint4*)&Alo[arr[i] * PITF + aq * 4] = make_uint4(l4[0], l4[1], l4[2], l4[3]);
            }
            {
                const float v[4] = { rB.x, rB.y, rB.z, rB.w };
                unsigned h4[4], l4[4];
#pragma unroll
                for (int e = 0; e < 4; e++) split_tf32(v[e], h4[e], l4[e]);
                *(uint4*)&Bhi[br * PITF + bq * 4] = make_uint4(h4[0], h4[1], h4[2], h4[3]);
                *(uint4*)&Blo[br * PITF + bq * 4] = make_uint4(l4[0], l4[1], l4[2], l4[3]);
            }
            __syncthreads();

            // ---- issue LDG for next chunk (latency hidden by compute) ----
            if (c + 1 < HID / KCS) {
                const int kc = (c + 1) * KCS;
#pragma unroll
                for (int i = 0; i < 4; i++)
                    rA[i] = *(const float4*)(hprev + (size_t)arr[i] * HID + kc + aq * 4);
                rB = *(const float4*)(Whh + (size_t)b_nglob * HID + kc + bq * 4);
            }

            // ---- mainloop: pure LDS + MMA; this warp's 2 kk-steps ----
#pragma unroll
            for (int kk2 = 0; kk2 < 2; kk2++) {
                const int kk = (ks * 2 + kk2) * 8;
                unsigned ahi[2][4], alo[2][4], bhi[4][2], blo[4][2];
#pragma unroll
                for (int mt = 0; mt < 2; mt++) {
                    int row = warp_m * 32 + mt * 16 + (lane >> 2);
                    int c0  = kk + (lane & 3);
                    ahi[mt][0] = *(unsigned*)&Ahi[row * PITF + c0];
                    ahi[mt][1] = *(unsigned*)&Ahi[(row + 8) * PITF + c0];
                    ahi[mt][2] = *(unsigned*)&Ahi[row * PITF + c0 + 4];
                    ahi[mt][3] = *(unsigned*)&Ahi[(row + 8) * PITF + c0 + 4];
                    alo[mt][0] = *(unsigned*)&Alo[row * PITF + c0];
                    alo[mt][1] = *(unsigned*)&Alo[(row + 8) * PITF + c0];
                    alo[mt][2] = *(unsigned*)&Alo[row * PITF + c0 + 4];
                    alo[mt][3] = *(unsigned*)&Alo[(row + 8) * PITF + c0 + 4];
                }
#pragma unroll
                for (int nt = 0; nt < 4; nt++) {
                    int brow = nt * 8 + (lane >> 2);
                    int bc   = kk + (lane & 3);
                    bhi[nt][0] = *(unsigned*)&Bhi[brow * PITF + bc];
                    bhi[nt][1] = *(unsigned*)&Bhi[brow * PITF + bc + 4];
                    blo[nt][0] = *(unsigned*)&Blo[brow * PITF + bc];
                    blo[nt][1] = *(unsigned*)&Blo[brow * PITF + bc + 4];
                }
#pragma unroll
                for (int mt = 0; mt < 2; mt++)
#pragma unroll
                    for (int nt = 0; nt < 4; nt++) {
                        mma_tf32(acc[mt][nt], ahi[mt], bhi[nt]);
                        mma_tf32(acc[mt][nt], ahi[mt], blo[nt]);
                        mma_tf32(acc[mt][nt], alo[mt], bhi[nt]);
                    }
            }
            __syncthreads();
        }
    }

    // stage K-partial gate pre-activations: gsm[ks][b][l], pitch 34
#pragma unroll
    for (int mt = 0; mt < 2; mt++)
#pragma unroll
        for (int nt = 0; nt < 4; nt++) {
            int row = warp_m * 32 + mt * 16 + (lane >> 2);
            int col = nt * 8 + (lane & 3) * 2;
            *(float2*)(gsm + ks * GSM_P + row * 34 + col) =
                make_float2(acc[mt][nt][0], acc[mt][nt][1]);
            *(float2*)(gsm + ks * GSM_P + (row + 8) * 34 + col) =
                make_float2(acc[mt][nt][2], acc[mt][nt][3]);
        }
    __syncthreads();

    // fused activation epilogue: 1024 (b, jj) items / 512 threads
    const float* xp   = g_xproj + (size_t)t * BATCH * G4;
    const float* cin  = g_c[t & 1];
    float*       cout = g_c[(t + 1) & 1];
    float*       hout = g_hs + (size_t)t * BATCH * HID;

#pragma unroll
    for (int it = 0; it < 2; it++) {
        int item = tid + it * 512;
        int b    = item & 127;
        int jj   = item >> 7;           // 0..7
        int j    = bx * 8 + jj;
        int base = b * 34 + jj * 4;
        float g0 = 0.f, g1 = 0.f, g2 = 0.f, g3 = 0.f;
#pragma unroll
        for (int p = 0; p < 4; p++) {
            g0 += gsm[p * GSM_P + base + 0];
            g1 += gsm[p * GSM_P + base + 1];
            g2 += gsm[p * GSM_P + base + 2];
            g3 += gsm[p * GSM_P + base + 3];
        }
        size_t xb = (size_t)b * G4 + j;
        float gi = g0 + xp[xb]           + bhh[j];
        float gf = g1 + xp[xb + HID]     + bhh[HID + j];
        float gg = g2 + xp[xb + 2 * HID] + bhh[2 * HID + j];
        float go = g3 + xp[xb + 3 * HID] + bhh[3 * HID + j];
        float cold = (t > 0) ? cin[b * HID + j] : 0.0f;
        float cn = sigmoidf_(gf) * cold + sigmoidf_(gi) * tanhf(gg);
        float hn = sigmoidf_(go) * tanhf(cn);
        cout[b * HID + j] = cn;
        hout[(size_t)b * HID + j] = hn;
    }
}

// ============================================================================
// In-place row-wise log_softmax over 256 columns. One block per row.
// ============================================================================
__launch_bounds__(256)
__global__ void logsoftmax_kernel(float* __restrict__ out) {
    __shared__ float red[256];
    const size_t r = blockIdx.x;
    const int tid  = threadIdx.x;
    float v = out[r * 256 + tid];

    red[tid] = v;
    __syncthreads();
#pragma unroll
    for (int s = 128; s > 0; s >>= 1) {
        if (tid < s) red[tid] = fmaxf(red[tid], red[tid + s]);
        __syncthreads();
    }
    float m = red[0];
    __syncthreads();

    float e = expf(v - m);
    red[tid] = e;
    __syncthreads();
#pragma unroll
    for (int s = 128; s > 0; s >>= 1) {
        if (tid < s) red[tid] += red[tid + s];
        __syncthreads();
    }
    float lse = logf(red[0]) + m;
    out[r * 256 + tid] = v - lse;
}

// ============================================================================
extern "C" void kernel_launch(void* const* d_in, const int* in_sizes, int n_in,
                              void* d_out, int out_size) {
    const float* inp  = (const float*)d_in[0];  // [512,128,256]
    const float* Wxh  = (const float*)d_in[1];  // [4096,256]
    const float* bxh  = (const float*)d_in[2];  // [4096]
    const float* Whh  = (const float*)d_in[3];  // [4096,1024]
    const float* bhh  = (const float*)d_in[4];  // [4096]
    const float* Wout = (const float*)d_in[5];  // [256,1024]
    const float* bout = (const float*)d_in[6];  // [256]
    float* out = (float*)d_out;                 // [512,128,256] fp32

    float* xproj; cudaGetSymbolAddress((void**)&xproj, g_xproj);
    float* hs;    cudaGetSymbolAddress((void**)&hs, g_hs);

    cudaFuncSetAttribute(lstm_step_tf32,
                         cudaFuncAttributeMaxDynamicSharedMemorySize, STEP_SMEM);
    cudaFuncSetAttribute(gemm_tf32,
                         cudaFuncAttributeMaxDynamicSharedMemorySize, GEMM_SMEM);

    // 1) x_proj[T*B, 4H] = inp @ Wxh^T + bxh  (3xTF32)
    gemm_tf32<<<dim3(G4 / 64, TB / 128), 256, GEMM_SMEM>>>(
        inp, Wxh, bxh, xproj, TB, G4, INPD);

    // 2) recurrence (3xTF32, fat warp tiles + 4-way K-split)
    for (int t = 0; t < SEQ; t++)
        lstm_step_tf32<<<128, 512, STEP_SMEM>>>(t, Whh, bhh);

    // 3) out[T*B, 256] = hs @ Wout^T + bout  (3xTF32)
    gemm_tf32<<<dim3(INPD / 64, TB / 128), 256, GEMM_SMEM>>>(
        hs, Wout, bout, out, TB, INPD, HID);

    // 4) log_softmax rows
    logsoftmax_kernel<<<TB, 256>>>(out);
}